// round 8
// baseline (speedup 1.0000x reference)
#include <cuda_runtime.h>
#include <cuda_bf16.h>

// NeuMIP v1, round 8: constant-memory weights (R7) + 2 points/thread so each
// uniform LDC.128 feeds both points' FFMA2s (halves the LDC bottleneck that
// bound R7 at ~253us). LDC ~127us vs FFMA2 floor ~137us -> balanced.

#define RESOL 512
#define RMASK 511
#define HID 32
#define NSLOPE 0.01f
#define THREADS 128
#define PTS_PER_BLOCK 256

typedef unsigned long long ull;

// Constant image: transposed weights [K][32] stored as packed neuron pairs.
struct __align__(16) CW {
    ulonglong2 ow0T[10 * 8];   // [10][32] floats
    ulonglong2 ow1T[32 * 8];
    ulonglong2 ow2T[32 * 8];
    ulonglong2 rw0T[12 * 8];
    ulonglong2 rw1T[32 * 8];
    ulonglong2 rw2T[32 * 8];
    ull ob0[16]; ull ob1[16]; ull ob2[16];
    ull rb0[16]; ull rb1[16]; ull rb2[16];
    ull ow3[16];               // [32] floats
    ull rw3[3][16];            // [3][32] floats
    float ob3; float rb3[3];
};

__constant__ CW cw;
__device__ CW g_stage;

__device__ __forceinline__ float leaky(float x) {
    return fmaxf(x, NSLOPE * x);  // slope < 1
}

__device__ __forceinline__ ull fma2(ull a, ull b, ull c) {
    ull d;
    asm("fma.rn.f32x2 %0, %1, %2, %3;" : "=l"(d) : "l"(a), "l"(b), "l"(c));
    return d;
}

__device__ __forceinline__ ull pack2(float lo, float hi) {
    ull d;
    asm("mov.b64 %0, {%1, %2};" : "=l"(d) : "f"(lo), "f"(hi));
    return d;
}

__device__ __forceinline__ void unpack2(ull v, float& lo, float& hi) {
    asm("mov.b64 {%0, %1}, %2;" : "=f"(lo), "=f"(hi) : "l"(v));
}

// ---------------- prep kernel: transpose + pack into g_stage ----------------

__device__ __forceinline__ void d_tpose(float* dst, const float* src, int K,
                                        int tid, int nt) {
    // src: [32][K] row-major -> dst: [K][32]
    for (int idx = tid; idx < HID * K; idx += nt) {
        int j = idx / K, i = idx - j * K;
        dst[i * HID + j] = src[idx];
    }
}

__device__ __forceinline__ void d_copy(float* dst, const float* src, int n,
                                       int tid, int nt) {
    for (int i = tid; i < n; i += nt) dst[i] = src[i];
}

__global__ void prep_kernel(const float* ow0, const float* ob0,
                            const float* ow1, const float* ob1,
                            const float* ow2, const float* ob2,
                            const float* ow3, const float* ob3,
                            const float* rw0, const float* rb0,
                            const float* rw1, const float* rb1,
                            const float* rw2, const float* rb2,
                            const float* rw3, const float* rb3) {
    const int tid = threadIdx.x, nt = blockDim.x;
    d_tpose((float*)g_stage.ow0T, ow0, 10, tid, nt);
    d_tpose((float*)g_stage.ow1T, ow1, 32, tid, nt);
    d_tpose((float*)g_stage.ow2T, ow2, 32, tid, nt);
    d_tpose((float*)g_stage.rw0T, rw0, 12, tid, nt);
    d_tpose((float*)g_stage.rw1T, rw1, 32, tid, nt);
    d_tpose((float*)g_stage.rw2T, rw2, 32, tid, nt);
    d_copy((float*)g_stage.ob0, ob0, 32, tid, nt);
    d_copy((float*)g_stage.ob1, ob1, 32, tid, nt);
    d_copy((float*)g_stage.ob2, ob2, 32, tid, nt);
    d_copy((float*)g_stage.rb0, rb0, 32, tid, nt);
    d_copy((float*)g_stage.rb1, rb1, 32, tid, nt);
    d_copy((float*)g_stage.rb2, rb2, 32, tid, nt);
    d_copy((float*)g_stage.ow3, ow3, 32, tid, nt);
    d_copy((float*)g_stage.rw3, rw3, 96, tid, nt);
    if (tid == 0) {
        g_stage.ob3 = ob3[0];
        g_stage.rb3[0] = rb3[0];
        g_stage.rb3[1] = rb3[1];
        g_stage.rb3[2] = rb3[2];
    }
}

// ---------------- main kernel ----------------

// 8-channel bilinear with wrap. Texel = 8 contiguous floats = 2x float4.
__device__ __forceinline__ void bilin8(const float4* __restrict__ t,
                                       float u, float v, float* __restrict__ o) {
    float px = u * (float)RESOL - 0.5f;
    float py = v * (float)RESOL - 0.5f;
    float fpx = floorf(px), fpy = floorf(py);
    float fx = px - fpx, fy = py - fpy;
    int ix = (int)fpx, iy = (int)fpy;
    int x0 = ix & RMASK, x1 = (ix + 1) & RMASK;
    int y0 = iy & RMASK, y1 = (iy + 1) & RMASK;
    float w00 = (1.0f - fx) * (1.0f - fy);
    float w01 = fx * (1.0f - fy);
    float w10 = (1.0f - fx) * fy;
    float w11 = fx * fy;
    const float4* p00 = t + (size_t)(y0 * RESOL + x0) * 2;
    const float4* p01 = t + (size_t)(y0 * RESOL + x1) * 2;
    const float4* p10 = t + (size_t)(y1 * RESOL + x0) * 2;
    const float4* p11 = t + (size_t)(y1 * RESOL + x1) * 2;
    float4 a00 = __ldg(p00),     b00 = __ldg(p00 + 1);
    float4 a01 = __ldg(p01),     b01 = __ldg(p01 + 1);
    float4 a10 = __ldg(p10),     b10 = __ldg(p10 + 1);
    float4 a11 = __ldg(p11),     b11 = __ldg(p11 + 1);
    o[0] = w00 * a00.x + w01 * a01.x + w10 * a10.x + w11 * a11.x;
    o[1] = w00 * a00.y + w01 * a01.y + w10 * a10.y + w11 * a11.y;
    o[2] = w00 * a00.z + w01 * a01.z + w10 * a10.z + w11 * a11.z;
    o[3] = w00 * a00.w + w01 * a01.w + w10 * a10.w + w11 * a11.w;
    o[4] = w00 * b00.x + w01 * b01.x + w10 * b10.x + w11 * b11.x;
    o[5] = w00 * b00.y + w01 * b01.y + w10 * b10.y + w11 * b11.y;
    o[6] = w00 * b00.z + w01 * b01.z + w10 * b10.z + w11 * b11.z;
    o[7] = w00 * b00.w + w01 * b01.w + w10 * b10.w + w11 * b11.w;
}

// One layer, 2 points, all 32 neurons. Each constant LDC.128 feeds FFMA2s
// for BOTH points.
template <int K>
__device__ __forceinline__ void layerC2(const ulonglong2* __restrict__ wT,
                                        const ull* __restrict__ bias,
                                        const float* __restrict__ in0,
                                        const float* __restrict__ in1,
                                        float* __restrict__ out0,
                                        float* __restrict__ out1) {
    ull acc0[16], acc1[16];
#pragma unroll
    for (int k = 0; k < 16; k++) { ull b = bias[k]; acc0[k] = b; acc1[k] = b; }
#pragma unroll
    for (int i = 0; i < K; i++) {
        ull a0 = pack2(in0[i], in0[i]);
        ull a1 = pack2(in1[i], in1[i]);
#pragma unroll
        for (int q = 0; q < 8; q++) {
            ulonglong2 w = wT[i * 8 + q];
            acc0[2 * q]     = fma2(a0, w.x, acc0[2 * q]);
            acc0[2 * q + 1] = fma2(a0, w.y, acc0[2 * q + 1]);
            acc1[2 * q]     = fma2(a1, w.x, acc1[2 * q]);
            acc1[2 * q + 1] = fma2(a1, w.y, acc1[2 * q + 1]);
        }
    }
#pragma unroll
    for (int k = 0; k < 16; k++) {
        float x, y;
        unpack2(acc0[k], x, y);
        out0[2 * k] = leaky(x); out0[2 * k + 1] = leaky(y);
        unpack2(acc1[k], x, y);
        out1[2 * k] = leaky(x); out1[2 * k + 1] = leaky(y);
    }
}

__device__ __forceinline__ float dotC(const ull* __restrict__ w,
                                      const float* __restrict__ v) {
    ull acc = pack2(0.0f, 0.0f);
#pragma unroll
    for (int k = 0; k < 16; k++) {
        acc = fma2(pack2(v[2 * k], v[2 * k + 1]), w[k], acc);
    }
    float lo, hi;
    unpack2(acc, lo, hi);
    return lo + hi;
}

__global__ void __launch_bounds__(THREADS, 3)
neumip_kernel(const float* __restrict__ cam,
              const float* __restrict__ light,
              const float* __restrict__ uv,
              const float* __restrict__ offset_tex,
              const float* __restrict__ rgb_tex,
              float* __restrict__ out, int n) {
    const int base = blockIdx.x * PTS_PER_BLOCK;
    const int p0 = base + threadIdx.x;
    const int p1 = p0 + THREADS;
    if (p0 >= n) return;

    const float2* cam2 = reinterpret_cast<const float2*>(cam);
    const float2* uv2p = reinterpret_cast<const float2*>(uv);
    const float2* li2 = reinterpret_cast<const float2*>(light);

    const float2 c0 = __ldg(cam2 + p0);
    const float2 c1 = __ldg(cam2 + p1);
    const float2 t0 = __ldg(uv2p + p0);
    const float2 t1 = __ldg(uv2p + p1);

    // ---- offset texture gather + depth MLP ----
    float in0[12], in1[12];
    bilin8(reinterpret_cast<const float4*>(offset_tex), t0.x, t0.y, in0);
    bilin8(reinterpret_cast<const float4*>(offset_tex), t1.x, t1.y, in1);
    in0[8] = c0.x; in0[9] = c0.y;
    in1[8] = c1.x; in1[9] = c1.y;

    float ha0[HID], ha1[HID], hb0[HID], hb1[HID];
    layerC2<10>(cw.ow0T, cw.ob0, in0, in1, ha0, ha1);
    layerC2<HID>(cw.ow1T, cw.ob1, ha0, ha1, hb0, hb1);
    layerC2<HID>(cw.ow2T, cw.ob2, hb0, hb1, ha0, ha1);

    float dep0 = dotC(cw.ow3, ha0) + cw.ob3;
    float dep1 = dotC(cw.ow3, ha1) + cw.ob3;

    // ---- parallax ----
    float z0 = sqrtf(fmaxf(1.0f - (c0.x * c0.x + c0.y * c0.y), 1e-6f));
    float z1 = sqrtf(fmaxf(1.0f - (c1.x * c1.x + c1.y * c1.y), 1e-6f));
    float s0 = dep0 / z0, s1 = dep1 / z1;
    float u10 = t0.x + c0.x * s0, v10 = t0.y + c0.y * s0;
    float u11 = t1.x + c1.x * s1, v11 = t1.y + c1.y * s1;

    // ---- rgb gather + rgb MLP ----
    const float2 l0 = __ldg(li2 + p0);
    const float2 l1 = __ldg(li2 + p1);
    in0[0] = l0.x; in0[1] = l0.y; in0[2] = c0.x; in0[3] = c0.y;
    in1[0] = l1.x; in1[1] = l1.y; in1[2] = c1.x; in1[3] = c1.y;
    bilin8(reinterpret_cast<const float4*>(rgb_tex), u10, v10, in0 + 4);
    bilin8(reinterpret_cast<const float4*>(rgb_tex), u11, v11, in1 + 4);

    layerC2<12>(cw.rw0T, cw.rb0, in0, in1, ha0, ha1);
    layerC2<HID>(cw.rw1T, cw.rb1, ha0, ha1, hb0, hb1);
    layerC2<HID>(cw.rw2T, cw.rb2, hb0, hb1, ha0, ha1);

#pragma unroll
    for (int c = 0; c < 3; c++) {
        out[3 * p0 + c] = dotC(cw.rw3[c], ha0) + cw.rb3[c];
        out[3 * p1 + c] = dotC(cw.rw3[c], ha1) + cw.rb3[c];
    }
}

extern "C" void kernel_launch(void* const* d_in, const int* in_sizes, int n_in,
                              void* d_out, int out_size) {
    const float* cam        = (const float*)d_in[0];
    const float* light      = (const float*)d_in[1];
    const float* uv         = (const float*)d_in[2];
    const float* offset_tex = (const float*)d_in[3];
    const float* rgb_tex    = (const float*)d_in[4];

    // 1) pack/transpose weights into device staging
    prep_kernel<<<1, 256>>>((const float*)d_in[5],  (const float*)d_in[6],
                            (const float*)d_in[7],  (const float*)d_in[8],
                            (const float*)d_in[9],  (const float*)d_in[10],
                            (const float*)d_in[11], (const float*)d_in[12],
                            (const float*)d_in[13], (const float*)d_in[14],
                            (const float*)d_in[15], (const float*)d_in[16],
                            (const float*)d_in[17], (const float*)d_in[18],
                            (const float*)d_in[19], (const float*)d_in[20]);

    // 2) device-to-device copy into the __constant__ image (capturable)
    void* stage_ptr = nullptr;
    cudaGetSymbolAddress(&stage_ptr, g_stage);
    cudaMemcpyToSymbolAsync(cw, stage_ptr, sizeof(CW), 0,
                            cudaMemcpyDeviceToDevice, 0);

    // 3) main kernel
    const int n = in_sizes[0] / 2;  // camera_dir is (B, 2)
    const int blocks = (n + PTS_PER_BLOCK - 1) / PTS_PER_BLOCK;
    neumip_kernel<<<blocks, THREADS>>>(cam, light, uv, offset_tex, rgb_tex,
                                       (float*)d_out, n);
}